// round 15
// baseline (speedup 1.0000x reference)
#include <cuda_runtime.h>
#include <math.h>

#define TS_   256
#define CTS_  512
#define B_    64
#define H_    512
#define K_    10
#define H3_   1536
#define TB_   16384
#define LOG2E 1.44269504088896340736f

static const int OFF_ATTK = TB_ * H_;
static const int OFF_ATTW = TB_ * H_ + TB_ * K_;

typedef unsigned long long u64;

// ---------------- static device scratch ----------------
__device__ float    g_a   [TB_ * K_];
__device__ float    g_b2  [TB_ * K_];
__device__ float    g_kinc[TB_ * K_];
__device__ float    g_phi [TB_ * CTS_];
__device__ float    g_gi  [TB_ * H3_];
__device__ float    g_h   [2 * B_ * H_];
__device__ unsigned g_cnt [128];     // GRU per-bg barriers
__device__ unsigned g_gicnt[128];    // gi per-m-strip completion (12 each)

__device__ __forceinline__ float ex2f(float x) {
    float r; asm("ex2.approx.ftz.f32 %0, %1;" : "=f"(r) : "f"(x)); return r;
}
__device__ __forceinline__ float sigmf(float x) { return 1.0f / (1.0f + __expf(-x)); }

__device__ __forceinline__ u64 pack2(float lo, float hi) {
    u64 r; asm("mov.b64 %0, {%1, %2};" : "=l"(r) : "f"(lo), "f"(hi)); return r;
}
__device__ __forceinline__ void unpack2(u64 v, float& lo, float& hi) {
    asm("mov.b64 {%0, %1}, %2;" : "=f"(lo), "=f"(hi) : "l"(v));
}
__device__ __forceinline__ u64 ffma2(u64 a, u64 b, u64 c) {
    u64 d; asm("fma.rn.f32x2 %0, %1, %2, %3;" : "=l"(d) : "l"(a), "l"(b), "l"(c)); return d;
}

// ---------------- K0: init counters ----------------
__global__ void k_init() {
    int i = threadIdx.x;
    if (i < 128) { g_cnt[i] = 0; g_gicnt[i] = 0; }
}

// ---------------- K1: a_t, b_t, kinc_t ----------------
__global__ __launch_bounds__(256) void k_abk(
    const float* __restrict__ inp,
    const float* __restrict__ Wa, const float* __restrict__ ba,
    const float* __restrict__ Wb, const float* __restrict__ bb,
    const float* __restrict__ Wk, const float* __restrict__ bk)
{
    __shared__ float xs[8 * 516];
    int tid = threadIdx.x;
    int r0 = blockIdx.x * 8;
    #pragma unroll
    for (int c = 0; c < 4; c++) {
        int fi = c * 256 + tid;
        int r = fi >> 7, hq = fi & 127;
        float4 v = *(const float4*)&inp[(r0 + r) * 512 + hq * 4];
        *(float4*)&xs[r * 516 + hq * 4] = v;
    }
    __syncthreads();

    int r = tid >> 5, o = tid & 31;
    if (o >= 30) return;
    const float* wrow; float bias;
    if (o < 10)      { wrow = Wa + o * 512;        bias = ba[o]; }
    else if (o < 20) { wrow = Wb + (o - 10) * 512; bias = bb[o - 10]; }
    else             { wrow = Wk + (o - 20) * 512; bias = bk[o - 20]; }

    const float4* xp = (const float4*)&xs[r * 516];
    const float4* wp = (const float4*)wrow;
    float a0 = 0.f, a1 = 0.f, a2 = 0.f, a3 = 0.f;
    #pragma unroll 8
    for (int q = 0; q < 128; q++) {
        float4 x = xp[q];
        float4 w = __ldg(&wp[q]);
        a0 += x.x * w.x; a1 += x.y * w.y; a2 += x.z * w.z; a3 += x.w * w.w;
    }
    float v = expf((a0 + a1) + (a2 + a3) + bias);
    int row = r0 + r;
    if (o < 10)      g_a   [row * 10 + o]        = v;
    else if (o < 20) g_b2  [row * 10 + (o - 10)] = v * LOG2E;
    else             g_kinc[row * 10 + (o - 20)] = v;
}

// ---------------- K2: cumulative k_t ----------------
__global__ void k_cumsum(const float* __restrict__ att_init, float* __restrict__ out) {
    int j = blockIdx.x * 128 + threadIdx.x;
    if (j >= 640) return;
    float acc = att_init[j];
    #pragma unroll 8
    for (int t = 0; t < TS_; t++) {
        acc += g_kinc[t * 640 + j];
        g_kinc[t * 640 + j] = acc;
        out[OFF_ATTK + t * 640 + j] = acc;
    }
}

// ---------------- K3: phi ----------------
__global__ __launch_bounds__(512) void k_phi() {
    __shared__ float sa[10], sb[10], sk[10];
    int row = blockIdx.x;
    int tid = threadIdx.x;
    if (tid < 10)       sa[tid]      = g_a   [row * 10 + tid];
    else if (tid < 20)  sb[tid - 10] = g_b2  [row * 10 + tid - 10];
    else if (tid < 30)  sk[tid - 20] = g_kinc[row * 10 + tid - 20];
    __syncthreads();
    float s = (float)tid;
    float acc = 0.f;
    #pragma unroll
    for (int k = 0; k < 10; k++) {
        float d = sk[k] - s;
        float e = sb[k] * d * d;
        if (e < 30.f) acc += sa[k] * ex2f(-e);
    }
    g_phi[row * 512 + tid] = acc;
}

// ---------------- GEMM common (R3 proven): 128x128 tile, 8x8/thread, f32x2 ----------------
#define AST 264
#define BST 132

__global__ __launch_bounds__(256, 2) void k_gemm_w(
    const float* __restrict__ c_inp, float* __restrict__ outw)
{
    __shared__ float As2[16 * AST];
    __shared__ float Bs [16 * BST];
    int tid = threadIdx.x;
    int b  = blockIdx.z;
    int m0 = blockIdx.y * 128, n0 = blockIdx.x * 128;

    int lrow = tid >> 2, lq = tid & 3;
    const float* Ap0 = g_phi + b * 512 + (m0 + lrow) * 32768 + lq * 4;
    const float* Ap1 = Ap0 + 64 * 32768;
    int lk = tid >> 5, nq = tid & 31;
    const float* Bp0 = c_inp + b * 512 + lk * 32768 + n0 + nq * 4;
    const float* Bp1 = Bp0 + 8 * 32768;

    float4 aR0 = *(const float4*)(Ap0);
    float4 aR1 = *(const float4*)(Ap1);
    float4 bR0 = *(const float4*)(Bp0);
    float4 bR1 = *(const float4*)(Bp1);

    int tx = tid & 15, ty = tid >> 4;
    u64 acc[8][4];
    #pragma unroll
    for (int i = 0; i < 8; i++)
        #pragma unroll
        for (int j = 0; j < 4; j++) acc[i][j] = 0ull;

    for (int kt = 0; kt < 32; kt++) {
        __syncthreads();
        {
            int m = 2 * lrow;
            *(u64*)&As2[(lq * 4 + 0) * AST + m]       = pack2(aR0.x, aR0.x);
            *(u64*)&As2[(lq * 4 + 1) * AST + m]       = pack2(aR0.y, aR0.y);
            *(u64*)&As2[(lq * 4 + 2) * AST + m]       = pack2(aR0.z, aR0.z);
            *(u64*)&As2[(lq * 4 + 3) * AST + m]       = pack2(aR0.w, aR0.w);
            *(u64*)&As2[(lq * 4 + 0) * AST + m + 128] = pack2(aR1.x, aR1.x);
            *(u64*)&As2[(lq * 4 + 1) * AST + m + 128] = pack2(aR1.y, aR1.y);
            *(u64*)&As2[(lq * 4 + 2) * AST + m + 128] = pack2(aR1.z, aR1.z);
            *(u64*)&As2[(lq * 4 + 3) * AST + m + 128] = pack2(aR1.w, aR1.w);
            *(float4*)&Bs[lk * BST + nq * 4]       = bR0;
            *(float4*)&Bs[(lk + 8) * BST + nq * 4] = bR1;
        }
        __syncthreads();
        if (kt < 31) {
            aR0 = *(const float4*)(Ap0 + (kt + 1) * 16);
            aR1 = *(const float4*)(Ap1 + (kt + 1) * 16);
            bR0 = *(const float4*)(Bp0 + (kt + 1) * 16 * 32768);
            bR1 = *(const float4*)(Bp1 + (kt + 1) * 16 * 32768);
        }
        #pragma unroll
        for (int kk = 0; kk < 16; kk++) {
            ulonglong2 a01 = *(const ulonglong2*)&As2[kk * AST + 8 * ty];
            ulonglong2 a23 = *(const ulonglong2*)&As2[kk * AST + 8 * ty + 4];
            ulonglong2 a45 = *(const ulonglong2*)&As2[kk * AST + 8 * ty + 128];
            ulonglong2 a67 = *(const ulonglong2*)&As2[kk * AST + 8 * ty + 132];
            ulonglong2 b01 = *(const ulonglong2*)&Bs[kk * BST + tx * 4];
            ulonglong2 b23 = *(const ulonglong2*)&Bs[kk * BST + tx * 4 + 64];
            u64 av[8] = {a01.x, a01.y, a23.x, a23.y, a45.x, a45.y, a67.x, a67.y};
            u64 bv[4] = {b01.x, b01.y, b23.x, b23.y};
            #pragma unroll
            for (int i = 0; i < 8; i++)
                #pragma unroll
                for (int j = 0; j < 4; j++)
                    acc[i][j] = ffma2(av[i], bv[j], acc[i][j]);
        }
    }
    float* C = outw + b * 512;
    #pragma unroll
    for (int i = 0; i < 8; i++) {
        int m = m0 + ((i < 4) ? (ty * 4 + i) : (ty * 4 + 64 + i - 4));
        float c0, c1, c2, c3;
        unpack2(acc[i][0], c0, c1); unpack2(acc[i][1], c2, c3);
        *(float4*)&C[(size_t)m * 32768 + n0 + tx * 4] = make_float4(c0, c1, c2, c3);
        unpack2(acc[i][2], c0, c1); unpack2(acc[i][3], c2, c3);
        *(float4*)&C[(size_t)m * 32768 + n0 + tx * 4 + 64] = make_float4(c0, c1, c2, c3);
    }
}

// K5: gi = w @ W_ih^T + b_ih  (+ per-m-strip completion counter)
__global__ __launch_bounds__(256, 2) void k_gemm_gi(
    const float* __restrict__ w, const float* __restrict__ W_ih,
    const float* __restrict__ b_ih)
{
    __shared__ float As2[16 * AST];
    __shared__ float Bs [16 * BST];
    int tid = threadIdx.x;
    int m0 = blockIdx.y * 128, n0 = blockIdx.x * 128;

    int lrow = tid >> 2, lq = tid & 3;
    const float* Ap0 = w + (m0 + lrow) * 512 + lq * 4;
    const float* Ap1 = Ap0 + 64 * 512;
    const float* Bp0 = W_ih + (n0 + lrow) * 512 + lq * 4;
    const float* Bp1 = Bp0 + 64 * 512;

    float4 aR0 = *(const float4*)(Ap0);
    float4 aR1 = *(const float4*)(Ap1);
    float4 bR0 = *(const float4*)(Bp0);
    float4 bR1 = *(const float4*)(Bp1);

    int tx = tid & 15, ty = tid >> 4;
    u64 acc[8][4];
    #pragma unroll
    for (int i = 0; i < 8; i++)
        #pragma unroll
        for (int j = 0; j < 4; j++) acc[i][j] = 0ull;

    for (int kt = 0; kt < 32; kt++) {
        __syncthreads();
        {
            int m = 2 * lrow;
            *(u64*)&As2[(lq * 4 + 0) * AST + m]       = pack2(aR0.x, aR0.x);
            *(u64*)&As2[(lq * 4 + 1) * AST + m]       = pack2(aR0.y, aR0.y);
            *(u64*)&As2[(lq * 4 + 2) * AST + m]       = pack2(aR0.z, aR0.z);
            *(u64*)&As2[(lq * 4 + 3) * AST + m]       = pack2(aR0.w, aR0.w);
            *(u64*)&As2[(lq * 4 + 0) * AST + m + 128] = pack2(aR1.x, aR1.x);
            *(u64*)&As2[(lq * 4 + 1) * AST + m + 128] = pack2(aR1.y, aR1.y);
            *(u64*)&As2[(lq * 4 + 2) * AST + m + 128] = pack2(aR1.z, aR1.z);
            *(u64*)&As2[(lq * 4 + 3) * AST + m + 128] = pack2(aR1.w, aR1.w);
            Bs[(lq * 4 + 0) * BST + lrow]       = bR0.x;
            Bs[(lq * 4 + 1) * BST + lrow]       = bR0.y;
            Bs[(lq * 4 + 2) * BST + lrow]       = bR0.z;
            Bs[(lq * 4 + 3) * BST + lrow]       = bR0.w;
            Bs[(lq * 4 + 0) * BST + lrow + 64]  = bR1.x;
            Bs[(lq * 4 + 1) * BST + lrow + 64]  = bR1.y;
            Bs[(lq * 4 + 2) * BST + lrow + 64]  = bR1.z;
            Bs[(lq * 4 + 3) * BST + lrow + 64]  = bR1.w;
        }
        __syncthreads();
        if (kt < 31) {
            aR0 = *(const float4*)(Ap0 + (kt + 1) * 16);
            aR1 = *(const float4*)(Ap1 + (kt + 1) * 16);
            bR0 = *(const float4*)(Bp0 + (kt + 1) * 16);
            bR1 = *(const float4*)(Bp1 + (kt + 1) * 16);
        }
        #pragma unroll
        for (int kk = 0; kk < 16; kk++) {
            ulonglong2 a01 = *(const ulonglong2*)&As2[kk * AST + 8 * ty];
            ulonglong2 a23 = *(const ulonglong2*)&As2[kk * AST + 8 * ty + 4];
            ulonglong2 a45 = *(const ulonglong2*)&As2[kk * AST + 8 * ty + 128];
            ulonglong2 a67 = *(const ulonglong2*)&As2[kk * AST + 8 * ty + 132];
            ulonglong2 b01 = *(const ulonglong2*)&Bs[kk * BST + tx * 4];
            ulonglong2 b23 = *(const ulonglong2*)&Bs[kk * BST + tx * 4 + 64];
            u64 av[8] = {a01.x, a01.y, a23.x, a23.y, a45.x, a45.y, a67.x, a67.y};
            u64 bv[4] = {b01.x, b01.y, b23.x, b23.y};
            #pragma unroll
            for (int i = 0; i < 8; i++)
                #pragma unroll
                for (int j = 0; j < 4; j++)
                    acc[i][j] = ffma2(av[i], bv[j], acc[i][j]);
        }
    }
    float4 bias0 = *(const float4*)&b_ih[n0 + tx * 4];
    float4 bias1 = *(const float4*)&b_ih[n0 + tx * 4 + 64];
    #pragma unroll
    for (int i = 0; i < 8; i++) {
        int m = m0 + ((i < 4) ? (ty * 4 + i) : (ty * 4 + 64 + i - 4));
        float c0, c1, c2, c3;
        unpack2(acc[i][0], c0, c1); unpack2(acc[i][1], c2, c3);
        *(float4*)&g_gi[(size_t)m * 1536 + n0 + tx * 4] =
            make_float4(c0 + bias0.x, c1 + bias0.y, c2 + bias0.z, c3 + bias0.w);
        unpack2(acc[i][2], c0, c1); unpack2(acc[i][3], c2, c3);
        *(float4*)&g_gi[(size_t)m * 1536 + n0 + tx * 4 + 64] =
            make_float4(c0 + bias1.x, c1 + bias1.y, c2 + bias1.z, c3 + bias1.w);
    }
    // publish strip progress
    __threadfence();
    __syncthreads();
    if (tid == 0) atomicAdd(&g_gicnt[blockIdx.y], 1u);
}

// ---------------- K6: warp-specialized persistent GRU (R8) + gi gating ----------------
#define HROW  516
#define HBUFF (16 * HROW)
#define GRU_SMEM ((2 * HBUFF + 48 * HROW) * 4)   // 165,120 B

__global__ __launch_bounds__(256, 1) void k_gru(
    const float* __restrict__ gru_init,
    const float* __restrict__ W_hh, const float* __restrict__ b_hh,
    float* __restrict__ out)
{
    extern __shared__ float sm[];
    float* hbuf = sm;                 // [2][16][HROW]
    float* Wsm  = sm + 2 * HBUFF;     // [48][HROW], row = gate*16 + u
    int tid = threadIdx.x;
    int ug = blockIdx.x, bg = blockIdx.y;

    for (int f = tid; f < 48 * 128; f += 256) {
        int rr = f >> 7, c = f & 127;
        int gate = rr >> 4, uu = rr & 15;
        float4 v = *(const float4*)&W_hh[((size_t)(gate * 512 + ug * 16 + uu)) * 512 + c * 4];
        *(float4*)&Wsm[rr * HROW + c * 4] = v;
    }
    __syncthreads();

    if (tid < 128) {
        // ================= compute warps =================
        int u  = tid >> 3;
        int bp = tid & 7;
        int gu  = ug * 16 + u;
        int gb0 = bg * 16 + bp;
        int gb1 = gb0 + 8;
        float bhr = b_hh[gu], bhz = b_hh[512 + gu], bhn = b_hh[1024 + gu];
        const float* wr = &Wsm[(0  + u) * HROW];
        const float* wz = &Wsm[(16 + u) * HROW];
        const float* wn = &Wsm[(32 + u) * HROW];
        int ready = -1;

        for (int t = 0; t < TS_; t++) {
            // gate on concurrent gi production (strip = 2 timesteps)
            int strip = t >> 1;
            if (ready < strip) {
                while (*((volatile unsigned*)&g_gicnt[strip]) < 12u) { }
                __threadfence();
                ready = strip;
            }
            const float* gp0 = g_gi + ((size_t)(t * 64 + gb0)) * 1536 + gu;
            const float* gp1 = g_gi + ((size_t)(t * 64 + gb1)) * 1536 + gu;
            float giR0 = __ldcs(gp0), giZ0 = __ldcs(gp0 + 512), giN0 = __ldcs(gp0 + 1024);
            float giR1 = __ldcs(gp1), giZ1 = __ldcs(gp1 + 512), giN1 = __ldcs(gp1 + 1024);

            asm volatile("bar.sync 1, 256;" ::: "memory");   // h_{t-1} staged

            const float* h0 = &hbuf[(t & 1) * HBUFF + bp * HROW];
            const float* h1 = h0 + 8 * HROW;
            u64 aR0 = 0, aZ0 = 0, aN0 = 0, aR1 = 0, aZ1 = 0, aN1 = 0;
            #pragma unroll 8
            for (int hh = 0; hh < 512; hh += 4) {
                ulonglong2 hv0 = *(const ulonglong2*)&h0[hh];
                ulonglong2 hv1 = *(const ulonglong2*)&h1[hh];
                ulonglong2 r2 = *(const ulonglong2*)&wr[hh];
                ulonglong2 z2 = *(const ulonglong2*)&wz[hh];
                ulonglong2 n2 = *(const ulonglong2*)&wn[hh];
                aR0 = ffma2(hv0.x, r2.x, aR0); aR0 = ffma2(hv0.y, r2.y, aR0);
                aZ0 = ffma2(hv0.x, z2.x, aZ0); aZ0 = ffma2(hv0.y, z2.y, aZ0);
                aN0 = ffma2(hv0.x, n2.x, aN0); aN0 = ffma2(hv0.y, n2.y, aN0);
                aR1 = ffma2(hv1.x, r2.x, aR1); aR1 = ffma2(hv1.y, r2.y, aR1);
                aZ1 = ffma2(hv1.x, z2.x, aZ1); aZ1 = ffma2(hv1.y, z2.y, aZ1);
                aN1 = ffma2(hv1.x, n2.x, aN1); aN1 = ffma2(hv1.y, n2.y, aN1);
            }
            float lo, hi;
            unpack2(aR0, lo, hi); float sR0 = lo + hi;
            unpack2(aZ0, lo, hi); float sZ0 = lo + hi;
            unpack2(aN0, lo, hi); float sN0 = lo + hi;
            unpack2(aR1, lo, hi); float sR1 = lo + hi;
            unpack2(aZ1, lo, hi); float sZ1 = lo + hi;
            unpack2(aN1, lo, hi); float sN1 = lo + hi;

            float hp0 = hbuf[(t & 1) * HBUFF + bp * HROW + gu];
            float hp1 = hbuf[(t & 1) * HBUFF + (bp + 8) * HROW + gu];
            float r0 = sigmf(giR0 + sR0 + bhr);
            float z0 = sigmf(giZ0 + sZ0 + bhz);
            float n0v = tanhf(giN0 + r0 * (sN0 + bhn));
            float hn0 = (1.f - z0) * n0v + z0 * hp0;
            float r1 = sigmf(giR1 + sR1 + bhr);
            float z1 = sigmf(giZ1 + sZ1 + bhz);
            float n1v = tanhf(giN1 + r1 * (sN1 + bhn));
            float hn1 = (1.f - z1) * n1v + z1 * hp1;

            g_h[((t + 1) & 1) * 32768 + gb0 * 512 + gu] = hn0;
            g_h[((t + 1) & 1) * 32768 + gb1 * 512 + gu] = hn1;
            asm volatile("bar.sync 2, 128;" ::: "memory");
            if (tid == 0) {
                __threadfence();
                atomicAdd(&g_cnt[bg * 32], 1u);
            }
            out[(size_t)t * 32768 + gb0 * 512 + gu] = hn0;
            out[(size_t)t * 32768 + gb1 * 512 + gu] = hn1;
        }
    } else {
        // ================= staging warps =================
        int stid = tid - 128;
        volatile unsigned* bar = &g_cnt[bg * 32];
        for (int t = 0; t < TS_; t++) {
            const float4* src;
            if (t == 0) {
                src = (const float4*)(gru_init + bg * 8192);
            } else {
                if (stid == 0) {
                    unsigned target = 32u * (unsigned)t;
                    while (*bar < target) { }
                    __threadfence();
                }
                asm volatile("bar.sync 3, 128;" ::: "memory");
                src = (const float4*)(g_h + (t & 1) * 32768 + bg * 8192);
            }
            float* dst = &hbuf[(t & 1) * HBUFF];
            #pragma unroll
            for (int c = 0; c < 16; c++) {
                int i = c * 128 + stid;
                float4 v = __ldcg(&src[i]);
                *(float4*)&dst[(i >> 7) * HROW + (i & 127) * 4] = v;
            }
            asm volatile("bar.sync 1, 256;" ::: "memory");
        }
    }
}

// ---------------- host ----------------
extern "C" void kernel_launch(void* const* d_in, const int* in_sizes, int n_in,
                              void* d_out, int out_size)
{
    const float* c_inp    = (const float*)d_in[0];
    const float* inp      = (const float*)d_in[1];
    const float* gru_init = (const float*)d_in[2];
    const float* att_init = (const float*)d_in[3];
    const float* Wa = (const float*)d_in[4];  const float* ba = (const float*)d_in[5];
    const float* Wb = (const float*)d_in[6];  const float* bb = (const float*)d_in[7];
    const float* Wk = (const float*)d_in[8];  const float* bk = (const float*)d_in[9];
    const float* W_ih = (const float*)d_in[10]; const float* b_ih = (const float*)d_in[11];
    const float* W_hh = (const float*)d_in[12]; const float* b_hh = (const float*)d_in[13];
    float* out = (float*)d_out;

    static cudaStream_t s2 = 0;
    static cudaEvent_t e1 = 0, e2 = 0;
    if (s2 == 0) {
        cudaStreamCreateWithFlags(&s2, cudaStreamNonBlocking);
        cudaEventCreateWithFlags(&e1, cudaEventDisableTiming);
        cudaEventCreateWithFlags(&e2, cudaEventDisableTiming);
        cudaFuncSetAttribute(k_gru, cudaFuncAttributeMaxDynamicSharedMemorySize, GRU_SMEM);
    }

    k_init   <<<1, 128>>>();
    k_abk    <<<2048, 256>>>(inp, Wa, ba, Wb, bb, Wk, bk);
    k_cumsum <<<5, 128>>>(att_init, out);
    k_phi    <<<16384, 512>>>();
    k_gemm_w <<<dim3(4, 2, 64), 256>>>(c_inp, out + OFF_ATTW);

    // fork: gru on stream 0 (launched first, grabs its SMs),
    //       gi on side stream (fills free SMs + co-resident slots)
    cudaEventRecord(e1, 0);
    k_gru    <<<dim3(32, 4), 256, GRU_SMEM>>>(gru_init, W_hh, b_hh, out);
    cudaStreamWaitEvent(s2, e1, 0);
    k_gemm_gi<<<dim3(12, 128), 256, 0, s2>>>(out + OFF_ATTW, W_ih, b_ih);
    cudaEventRecord(e2, s2);
    cudaStreamWaitEvent(0, e2, 0);
}

// round 16
// speedup vs baseline: 1.5299x; 1.5299x over previous
#include <cuda_runtime.h>
#include <math.h>

#define TS_   256
#define CTS_  512
#define B_    64
#define H_    512
#define K_    10
#define H3_   1536
#define TB_   16384
#define LOG2E 1.44269504088896340736f

static const int OFF_ATTK = TB_ * H_;
static const int OFF_ATTW = TB_ * H_ + TB_ * K_;

typedef unsigned long long u64;

// ---------------- static device scratch ----------------
__device__ float    g_a   [TB_ * K_];
__device__ float    g_b2  [TB_ * K_];
__device__ float    g_kinc[TB_ * K_];
__device__ float    g_phi [TB_ * CTS_];
__device__ float    g_gi  [TB_ * H3_];
__device__ float    g_h   [2 * B_ * H_];
__device__ unsigned g_bar4[128];          // 4 barriers, padded

__device__ __forceinline__ float ex2f(float x) {
    float r; asm("ex2.approx.ftz.f32 %0, %1;" : "=f"(r) : "f"(x)); return r;
}
__device__ __forceinline__ float sigmf(float x) { return 1.0f / (1.0f + __expf(-x)); }

__device__ __forceinline__ u64 pack2(float lo, float hi) {
    u64 r; asm("mov.b64 %0, {%1, %2};" : "=l"(r) : "f"(lo), "f"(hi)); return r;
}
__device__ __forceinline__ void unpack2(u64 v, float& lo, float& hi) {
    asm("mov.b64 {%0, %1}, %2;" : "=f"(lo), "=f"(hi) : "l"(v));
}
__device__ __forceinline__ u64 ffma2(u64 a, u64 b, u64 c) {
    u64 d; asm("fma.rn.f32x2 %0, %1, %2, %3;" : "=l"(d) : "l"(a), "l"(b), "l"(c)); return d;
}

// ---------------- K0: init ----------------
__global__ void k_init() {
    if (threadIdx.x < 128) g_bar4[threadIdx.x] = 0;
}

// ---------------- K1: a_t, b_t, kinc_t ----------------
__global__ __launch_bounds__(256) void k_abk(
    const float* __restrict__ inp,
    const float* __restrict__ Wa, const float* __restrict__ ba,
    const float* __restrict__ Wb, const float* __restrict__ bb,
    const float* __restrict__ Wk, const float* __restrict__ bk)
{
    __shared__ float xs[8 * 516];
    int tid = threadIdx.x;
    int r0 = blockIdx.x * 8;
    #pragma unroll
    for (int c = 0; c < 4; c++) {
        int fi = c * 256 + tid;
        int r = fi >> 7, hq = fi & 127;
        float4 v = *(const float4*)&inp[(r0 + r) * 512 + hq * 4];
        *(float4*)&xs[r * 516 + hq * 4] = v;
    }
    __syncthreads();

    int r = tid >> 5, o = tid & 31;
    if (o >= 30) return;
    const float* wrow; float bias;
    if (o < 10)      { wrow = Wa + o * 512;        bias = ba[o]; }
    else if (o < 20) { wrow = Wb + (o - 10) * 512; bias = bb[o - 10]; }
    else             { wrow = Wk + (o - 20) * 512; bias = bk[o - 20]; }

    const float4* xp = (const float4*)&xs[r * 516];
    const float4* wp = (const float4*)wrow;
    float a0 = 0.f, a1 = 0.f, a2 = 0.f, a3 = 0.f;
    #pragma unroll 8
    for (int q = 0; q < 128; q++) {
        float4 x = xp[q];
        float4 w = __ldg(&wp[q]);
        a0 += x.x * w.x; a1 += x.y * w.y; a2 += x.z * w.z; a3 += x.w * w.w;
    }
    float v = expf((a0 + a1) + (a2 + a3) + bias);
    int row = r0 + r;
    if (o < 10)      g_a   [row * 10 + o]        = v;
    else if (o < 20) g_b2  [row * 10 + (o - 10)] = v * LOG2E;
    else             g_kinc[row * 10 + (o - 20)] = v;
}

// ---------------- K2: cumulative k_t ----------------
__global__ void k_cumsum(const float* __restrict__ att_init, float* __restrict__ out) {
    int j = blockIdx.x * 128 + threadIdx.x;
    if (j >= 640) return;
    float acc = att_init[j];
    #pragma unroll 8
    for (int t = 0; t < TS_; t++) {
        acc += g_kinc[t * 640 + j];
        g_kinc[t * 640 + j] = acc;
        out[OFF_ATTK + t * 640 + j] = acc;
    }
}

// ---------------- K3: phi ----------------
__global__ __launch_bounds__(512) void k_phi() {
    __shared__ float sa[10], sb[10], sk[10];
    int row = blockIdx.x;
    int tid = threadIdx.x;
    if (tid < 10)       sa[tid]      = g_a   [row * 10 + tid];
    else if (tid < 20)  sb[tid - 10] = g_b2  [row * 10 + tid - 10];
    else if (tid < 30)  sk[tid - 20] = g_kinc[row * 10 + tid - 20];
    __syncthreads();
    float s = (float)tid;
    float acc = 0.f;
    #pragma unroll
    for (int k = 0; k < 10; k++) {
        float d = sk[k] - s;
        float e = sb[k] * d * d;
        if (e < 30.f) acc += sa[k] * ex2f(-e);
    }
    g_phi[row * 512 + tid] = acc;
}

// ---------------- GEMM common (R3 proven): 128x128 tile, 8x8/thread, f32x2 ----------------
#define AST 264
#define BST 132

__global__ __launch_bounds__(256, 2) void k_gemm_w(
    const float* __restrict__ c_inp, float* __restrict__ outw)
{
    __shared__ float As2[16 * AST];
    __shared__ float Bs [16 * BST];
    int tid = threadIdx.x;
    int b  = blockIdx.z;
    int m0 = blockIdx.y * 128, n0 = blockIdx.x * 128;

    int lrow = tid >> 2, lq = tid & 3;
    const float* Ap0 = g_phi + b * 512 + (m0 + lrow) * 32768 + lq * 4;
    const float* Ap1 = Ap0 + 64 * 32768;
    int lk = tid >> 5, nq = tid & 31;
    const float* Bp0 = c_inp + b * 512 + lk * 32768 + n0 + nq * 4;
    const float* Bp1 = Bp0 + 8 * 32768;

    float4 aR0 = *(const float4*)(Ap0);
    float4 aR1 = *(const float4*)(Ap1);
    float4 bR0 = *(const float4*)(Bp0);
    float4 bR1 = *(const float4*)(Bp1);

    int tx = tid & 15, ty = tid >> 4;
    u64 acc[8][4];
    #pragma unroll
    for (int i = 0; i < 8; i++)
        #pragma unroll
        for (int j = 0; j < 4; j++) acc[i][j] = 0ull;

    for (int kt = 0; kt < 32; kt++) {
        __syncthreads();
        {
            int m = 2 * lrow;
            *(u64*)&As2[(lq * 4 + 0) * AST + m]       = pack2(aR0.x, aR0.x);
            *(u64*)&As2[(lq * 4 + 1) * AST + m]       = pack2(aR0.y, aR0.y);
            *(u64*)&As2[(lq * 4 + 2) * AST + m]       = pack2(aR0.z, aR0.z);
            *(u64*)&As2[(lq * 4 + 3) * AST + m]       = pack2(aR0.w, aR0.w);
            *(u64*)&As2[(lq * 4 + 0) * AST + m + 128] = pack2(aR1.x, aR1.x);
            *(u64*)&As2[(lq * 4 + 1) * AST + m + 128] = pack2(aR1.y, aR1.y);
            *(u64*)&As2[(lq * 4 + 2) * AST + m + 128] = pack2(aR1.z, aR1.z);
            *(u64*)&As2[(lq * 4 + 3) * AST + m + 128] = pack2(aR1.w, aR1.w);
            *(float4*)&Bs[lk * BST + nq * 4]       = bR0;
            *(float4*)&Bs[(lk + 8) * BST + nq * 4] = bR1;
        }
        __syncthreads();
        if (kt < 31) {
            aR0 = *(const float4*)(Ap0 + (kt + 1) * 16);
            aR1 = *(const float4*)(Ap1 + (kt + 1) * 16);
            bR0 = *(const float4*)(Bp0 + (kt + 1) * 16 * 32768);
            bR1 = *(const float4*)(Bp1 + (kt + 1) * 16 * 32768);
        }
        #pragma unroll
        for (int kk = 0; kk < 16; kk++) {
            ulonglong2 a01 = *(const ulonglong2*)&As2[kk * AST + 8 * ty];
            ulonglong2 a23 = *(const ulonglong2*)&As2[kk * AST + 8 * ty + 4];
            ulonglong2 a45 = *(const ulonglong2*)&As2[kk * AST + 8 * ty + 128];
            ulonglong2 a67 = *(const ulonglong2*)&As2[kk * AST + 8 * ty + 132];
            ulonglong2 b01 = *(const ulonglong2*)&Bs[kk * BST + tx * 4];
            ulonglong2 b23 = *(const ulonglong2*)&Bs[kk * BST + tx * 4 + 64];
            u64 av[8] = {a01.x, a01.y, a23.x, a23.y, a45.x, a45.y, a67.x, a67.y};
            u64 bv[4] = {b01.x, b01.y, b23.x, b23.y};
            #pragma unroll
            for (int i = 0; i < 8; i++)
                #pragma unroll
                for (int j = 0; j < 4; j++)
                    acc[i][j] = ffma2(av[i], bv[j], acc[i][j]);
        }
    }
    float* C = outw + b * 512;
    #pragma unroll
    for (int i = 0; i < 8; i++) {
        int m = m0 + ((i < 4) ? (ty * 4 + i) : (ty * 4 + 64 + i - 4));
        float c0, c1, c2, c3;
        unpack2(acc[i][0], c0, c1); unpack2(acc[i][1], c2, c3);
        *(float4*)&C[(size_t)m * 32768 + n0 + tx * 4] = make_float4(c0, c1, c2, c3);
        unpack2(acc[i][2], c0, c1); unpack2(acc[i][3], c2, c3);
        *(float4*)&C[(size_t)m * 32768 + n0 + tx * 4 + 64] = make_float4(c0, c1, c2, c3);
    }
}

__global__ __launch_bounds__(256, 2) void k_gemm_gi(
    const float* __restrict__ w, const float* __restrict__ W_ih,
    const float* __restrict__ b_ih)
{
    __shared__ float As2[16 * AST];
    __shared__ float Bs [16 * BST];
    int tid = threadIdx.x;
    int m0 = blockIdx.y * 128, n0 = blockIdx.x * 128;

    int lrow = tid >> 2, lq = tid & 3;
    const float* Ap0 = w + (m0 + lrow) * 512 + lq * 4;
    const float* Ap1 = Ap0 + 64 * 512;
    const float* Bp0 = W_ih + (n0 + lrow) * 512 + lq * 4;
    const float* Bp1 = Bp0 + 64 * 512;

    float4 aR0 = *(const float4*)(Ap0);
    float4 aR1 = *(const float4*)(Ap1);
    float4 bR0 = *(const float4*)(Bp0);
    float4 bR1 = *(const float4*)(Bp1);

    int tx = tid & 15, ty = tid >> 4;
    u64 acc[8][4];
    #pragma unroll
    for (int i = 0; i < 8; i++)
        #pragma unroll
        for (int j = 0; j < 4; j++) acc[i][j] = 0ull;

    for (int kt = 0; kt < 32; kt++) {
        __syncthreads();
        {
            int m = 2 * lrow;
            *(u64*)&As2[(lq * 4 + 0) * AST + m]       = pack2(aR0.x, aR0.x);
            *(u64*)&As2[(lq * 4 + 1) * AST + m]       = pack2(aR0.y, aR0.y);
            *(u64*)&As2[(lq * 4 + 2) * AST + m]       = pack2(aR0.z, aR0.z);
            *(u64*)&As2[(lq * 4 + 3) * AST + m]       = pack2(aR0.w, aR0.w);
            *(u64*)&As2[(lq * 4 + 0) * AST + m + 128] = pack2(aR1.x, aR1.x);
            *(u64*)&As2[(lq * 4 + 1) * AST + m + 128] = pack2(aR1.y, aR1.y);
            *(u64*)&As2[(lq * 4 + 2) * AST + m + 128] = pack2(aR1.z, aR1.z);
            *(u64*)&As2[(lq * 4 + 3) * AST + m + 128] = pack2(aR1.w, aR1.w);
            Bs[(lq * 4 + 0) * BST + lrow]       = bR0.x;
            Bs[(lq * 4 + 1) * BST + lrow]       = bR0.y;
            Bs[(lq * 4 + 2) * BST + lrow]       = bR0.z;
            Bs[(lq * 4 + 3) * BST + lrow]       = bR0.w;
            Bs[(lq * 4 + 0) * BST + lrow + 64]  = bR1.x;
            Bs[(lq * 4 + 1) * BST + lrow + 64]  = bR1.y;
            Bs[(lq * 4 + 2) * BST + lrow + 64]  = bR1.z;
            Bs[(lq * 4 + 3) * BST + lrow + 64]  = bR1.w;
        }
        __syncthreads();
        if (kt < 31) {
            aR0 = *(const float4*)(Ap0 + (kt + 1) * 16);
            aR1 = *(const float4*)(Ap1 + (kt + 1) * 16);
            bR0 = *(const float4*)(Bp0 + (kt + 1) * 16);
            bR1 = *(const float4*)(Bp1 + (kt + 1) * 16);
        }
        #pragma unroll
        for (int kk = 0; kk < 16; kk++) {
            ulonglong2 a01 = *(const ulonglong2*)&As2[kk * AST + 8 * ty];
            ulonglong2 a23 = *(const ulonglong2*)&As2[kk * AST + 8 * ty + 4];
            ulonglong2 a45 = *(const ulonglong2*)&As2[kk * AST + 8 * ty + 128];
            ulonglong2 a67 = *(const ulonglong2*)&As2[kk * AST + 8 * ty + 132];
            ulonglong2 b01 = *(const ulonglong2*)&Bs[kk * BST + tx * 4];
            ulonglong2 b23 = *(const ulonglong2*)&Bs[kk * BST + tx * 4 + 64];
            u64 av[8] = {a01.x, a01.y, a23.x, a23.y, a45.x, a45.y, a67.x, a67.y};
            u64 bv[4] = {b01.x, b01.y, b23.x, b23.y};
            #pragma unroll
            for (int i = 0; i < 8; i++)
                #pragma unroll
                for (int j = 0; j < 4; j++)
                    acc[i][j] = ffma2(av[i], bv[j], acc[i][j]);
        }
    }
    float4 bias0 = *(const float4*)&b_ih[n0 + tx * 4];
    float4 bias1 = *(const float4*)&b_ih[n0 + tx * 4 + 64];
    #pragma unroll
    for (int i = 0; i < 8; i++) {
        int m = m0 + ((i < 4) ? (ty * 4 + i) : (ty * 4 + 64 + i - 4));
        float c0, c1, c2, c3;
        unpack2(acc[i][0], c0, c1); unpack2(acc[i][1], c2, c3);
        *(float4*)&g_gi[(size_t)m * 1536 + n0 + tx * 4] =
            make_float4(c0 + bias0.x, c1 + bias0.y, c2 + bias0.z, c3 + bias0.w);
        unpack2(acc[i][2], c0, c1); unpack2(acc[i][3], c2, c3);
        *(float4*)&g_gi[(size_t)m * 1536 + n0 + tx * 4 + 64] =
            make_float4(c0 + bias1.x, c1 + bias1.y, c2 + bias1.z, c3 + bias1.w);
    }
}

// ---------------- K6: persistent sequential GRU (R3 proven + 3 tweaks) ----------------
// grid (32 ug, 4 bg) x 128 threads; thread: u = tid>>3 (16 units), bp = tid&7,
// handles batches bp and bp+8.
#define HS_ST 516
#define SMEM_GRU_BYTES ((48 + 16) * HS_ST * 4)

__global__ __launch_bounds__(128, 1) void k_gru(
    const float* __restrict__ gru_init,
    const float* __restrict__ W_hh, const float* __restrict__ b_hh,
    float* __restrict__ out)
{
    extern __shared__ float smemf[];
    float* hs  = smemf;               // [16][HS_ST]
    float* Wsm = smemf + 16 * HS_ST;  // [48][HS_ST], row = gate*16 + u
    int tid = threadIdx.x;
    int ug = blockIdx.x, bg = blockIdx.y;

    // stage W_hh slice (48 rows x 512)
    for (int f = tid; f < 48 * 128; f += 128) {
        int rr = f >> 7, c = f & 127;
        int gate = rr >> 4, uu = rr & 15;
        float4 v = *(const float4*)&W_hh[(gate * 512 + ug * 16 + uu) * 512 + c * 4];
        *(float4*)&Wsm[rr * HS_ST + c * 4] = v;
    }

    int u  = tid >> 3;
    int bp = tid & 7;
    int gu  = ug * 16 + u;
    int gb0 = bg * 16 + bp;
    int gb1 = gb0 + 8;
    float bhr = b_hh[gu], bhz = b_hh[512 + gu], bhn = b_hh[1024 + gu];
    const float* wr = &Wsm[(0  + u) * HS_ST];
    const float* wz = &Wsm[(16 + u) * HS_ST];
    const float* wn = &Wsm[(32 + u) * HS_ST];
    const float* h0 = &hs[bp * HS_ST];
    const float* h1 = &hs[(bp + 8) * HS_ST];
    unsigned bar_target = 0;
    volatile unsigned* bar = &g_bar4[bg * 32];
    __syncthreads();

    for (int t = 0; t < TS_; t++) {
        // gi prefetch (6 scalars)
        const float* gp0 = g_gi + (t * 64 + gb0) * 1536 + gu;
        const float* gp1 = g_gi + (t * 64 + gb1) * 1536 + gu;
        float giR0 = __ldcs(gp0), giZ0 = __ldcs(gp0 + 512), giN0 = __ldcs(gp0 + 1024);
        float giR1 = __ldcs(gp1), giZ1 = __ldcs(gp1 + 512), giN1 = __ldcs(gp1 + 1024);

        // stage h_{t-1}: 16 rows x 512 = 2048 float4 / 128 threads
        const float4* src = (t == 0)
            ? (const float4*)(gru_init + bg * 8192)
            : (const float4*)(g_h + (t & 1) * 32768 + bg * 8192);
        #pragma unroll
        for (int c = 0; c < 16; c++) {
            int i = c * 128 + tid;
            float4 v = __ldcg(&src[i]);
            *(float4*)&hs[(i >> 7) * HS_ST + (i & 127) * 4] = v;
        }
        __syncthreads();

        u64 aR0 = 0, aZ0 = 0, aN0 = 0, aR1 = 0, aZ1 = 0, aN1 = 0;
        #pragma unroll 8
        for (int hh = 0; hh < 512; hh += 4) {
            ulonglong2 hv0 = *(const ulonglong2*)&h0[hh];
            ulonglong2 hv1 = *(const ulonglong2*)&h1[hh];
            ulonglong2 r2 = *(const ulonglong2*)&wr[hh];
            ulonglong2 z2 = *(const ulonglong2*)&wz[hh];
            ulonglong2 n2 = *(const ulonglong2*)&wn[hh];
            aR0 = ffma2(hv0.x, r2.x, aR0); aR0 = ffma2(hv0.y, r2.y, aR0);
            aZ0 = ffma2(hv0.x, z2.x, aZ0); aZ0 = ffma2(hv0.y, z2.y, aZ0);
            aN0 = ffma2(hv0.x, n2.x, aN0); aN0 = ffma2(hv0.y, n2.y, aN0);
            aR1 = ffma2(hv1.x, r2.x, aR1); aR1 = ffma2(hv1.y, r2.y, aR1);
            aZ1 = ffma2(hv1.x, z2.x, aZ1); aZ1 = ffma2(hv1.y, z2.y, aZ1);
            aN1 = ffma2(hv1.x, n2.x, aN1); aN1 = ffma2(hv1.y, n2.y, aN1);
        }
        float lo, hi;
        unpack2(aR0, lo, hi); float sR0 = lo + hi;
        unpack2(aZ0, lo, hi); float sZ0 = lo + hi;
        unpack2(aN0, lo, hi); float sN0 = lo + hi;
        unpack2(aR1, lo, hi); float sR1 = lo + hi;
        unpack2(aZ1, lo, hi); float sZ1 = lo + hi;
        unpack2(aN1, lo, hi); float sN1 = lo + hi;

        float hp0 = h0[gu & 511];
        float hp1 = h1[gu & 511];
        float r0 = sigmf(giR0 + sR0 + bhr);
        float z0 = sigmf(giZ0 + sZ0 + bhz);
        float n0v = tanhf(giN0 + r0 * (sN0 + bhn));
        float hn0 = (1.f - z0) * n0v + z0 * hp0;
        float r1 = sigmf(giR1 + sR1 + bhr);
        float z1 = sigmf(giZ1 + sZ1 + bhz);
        float n1v = tanhf(giN1 + r1 * (sN1 + bhn));
        float hn1 = (1.f - z1) * n1v + z1 * hp1;

        if (t < TS_ - 1) {
            // publish h_t, release, then overlap out-writes with the poll
            g_h[((t + 1) & 1) * 32768 + gb0 * 512 + gu] = hn0;
            g_h[((t + 1) & 1) * 32768 + gb1 * 512 + gu] = hn1;
            __threadfence();                      // drains only the 2 h STGs
            __syncthreads();
            if (tid == 0) {
                bar_target += 32;
                atomicAdd((unsigned*)bar, 1u);
            }
            out[t * 32768 + gb0 * 512 + gu] = hn0;
            out[t * 32768 + gb1 * 512 + gu] = hn1;
            if (tid == 0) {
                while (*bar < bar_target) { }     // hot spin, no nanosleep
            }
            __syncthreads();
        } else {
            out[t * 32768 + gb0 * 512 + gu] = hn0;
            out[t * 32768 + gb1 * 512 + gu] = hn1;
        }
    }
}

// ---------------- host ----------------
extern "C" void kernel_launch(void* const* d_in, const int* in_sizes, int n_in,
                              void* d_out, int out_size)
{
    const float* c_inp    = (const float*)d_in[0];
    const float* inp      = (const float*)d_in[1];
    const float* gru_init = (const float*)d_in[2];
    const float* att_init = (const float*)d_in[3];
    const float* Wa = (const float*)d_in[4];  const float* ba = (const float*)d_in[5];
    const float* Wb = (const float*)d_in[6];  const float* bb = (const float*)d_in[7];
    const float* Wk = (const float*)d_in[8];  const float* bk = (const float*)d_in[9];
    const float* W_ih = (const float*)d_in[10]; const float* b_ih = (const float*)d_in[11];
    const float* W_hh = (const float*)d_in[12]; const float* b_hh = (const float*)d_in[13];
    float* out = (float*)d_out;

    cudaFuncSetAttribute(k_gru, cudaFuncAttributeMaxDynamicSharedMemorySize, SMEM_GRU_BYTES);

    k_init   <<<1, 128>>>();
    k_abk    <<<2048, 256>>>(inp, Wa, ba, Wb, bb, Wk, bk);
    k_cumsum <<<5, 128>>>(att_init, out);
    k_phi    <<<16384, 512>>>();
    k_gemm_w <<<dim3(4, 2, 64), 256>>>(c_inp, out + OFF_ATTW);
    k_gemm_gi<<<dim3(12, 128), 256>>>(out + OFF_ATTW, W_ih, b_ih);
    k_gru    <<<dim3(32, 4), 128, SMEM_GRU_BYTES>>>(gru_init, W_hh, b_hh, out);
}

// round 17
// speedup vs baseline: 1.5639x; 1.0222x over previous
#include <cuda_runtime.h>
#include <math.h>

#define TS_   256
#define CTS_  512
#define B_    64
#define H_    512
#define K_    10
#define H3_   1536
#define TB_   16384
#define LOG2E 1.44269504088896340736f

static const int OFF_ATTK = TB_ * H_;
static const int OFF_ATTW = TB_ * H_ + TB_ * K_;

typedef unsigned long long u64;

// ---------------- static device scratch ----------------
__device__ float    g_a   [TB_ * K_];
__device__ float    g_b2  [TB_ * K_];
__device__ float    g_kinc[TB_ * K_];
__device__ float    g_phi [TB_ * CTS_];
__device__ float    g_gi  [TB_ * H3_];
__device__ float    g_h   [2 * B_ * H_];
__device__ unsigned g_bar8[128];          // 8 barriers, spaced 16 words

__device__ __forceinline__ float ex2f(float x) {
    float r; asm("ex2.approx.ftz.f32 %0, %1;" : "=f"(r) : "f"(x)); return r;
}
__device__ __forceinline__ float sigmf(float x) { return 1.0f / (1.0f + __expf(-x)); }

__device__ __forceinline__ u64 pack2(float lo, float hi) {
    u64 r; asm("mov.b64 %0, {%1, %2};" : "=l"(r) : "f"(lo), "f"(hi)); return r;
}
__device__ __forceinline__ void unpack2(u64 v, float& lo, float& hi) {
    asm("mov.b64 {%0, %1}, %2;" : "=f"(lo), "=f"(hi) : "l"(v));
}
__device__ __forceinline__ u64 ffma2(u64 a, u64 b, u64 c) {
    u64 d; asm("fma.rn.f32x2 %0, %1, %2, %3;" : "=l"(d) : "l"(a), "l"(b), "l"(c)); return d;
}

// ---------------- K0: init ----------------
__global__ void k_init() {
    if (threadIdx.x < 128) g_bar8[threadIdx.x] = 0;
}

// ---------------- K1: a_t, b_t, kinc_t ----------------
__global__ __launch_bounds__(256) void k_abk(
    const float* __restrict__ inp,
    const float* __restrict__ Wa, const float* __restrict__ ba,
    const float* __restrict__ Wb, const float* __restrict__ bb,
    const float* __restrict__ Wk, const float* __restrict__ bk)
{
    __shared__ float xs[8 * 516];
    int tid = threadIdx.x;
    int r0 = blockIdx.x * 8;
    #pragma unroll
    for (int c = 0; c < 4; c++) {
        int fi = c * 256 + tid;
        int r = fi >> 7, hq = fi & 127;
        float4 v = *(const float4*)&inp[(r0 + r) * 512 + hq * 4];
        *(float4*)&xs[r * 516 + hq * 4] = v;
    }
    __syncthreads();

    int r = tid >> 5, o = tid & 31;
    if (o >= 30) return;
    const float* wrow; float bias;
    if (o < 10)      { wrow = Wa + o * 512;        bias = ba[o]; }
    else if (o < 20) { wrow = Wb + (o - 10) * 512; bias = bb[o - 10]; }
    else             { wrow = Wk + (o - 20) * 512; bias = bk[o - 20]; }

    const float4* xp = (const float4*)&xs[r * 516];
    const float4* wp = (const float4*)wrow;
    float a0 = 0.f, a1 = 0.f, a2 = 0.f, a3 = 0.f;
    #pragma unroll 8
    for (int q = 0; q < 128; q++) {
        float4 x = xp[q];
        float4 w = __ldg(&wp[q]);
        a0 += x.x * w.x; a1 += x.y * w.y; a2 += x.z * w.z; a3 += x.w * w.w;
    }
    float v = expf((a0 + a1) + (a2 + a3) + bias);
    int row = r0 + r;
    if (o < 10)      g_a   [row * 10 + o]        = v;
    else if (o < 20) g_b2  [row * 10 + (o - 10)] = v * LOG2E;
    else             g_kinc[row * 10 + (o - 20)] = v;
}

// ---------------- K2: cumulative k_t ----------------
__global__ void k_cumsum(const float* __restrict__ att_init, float* __restrict__ out) {
    int j = blockIdx.x * 128 + threadIdx.x;
    if (j >= 640) return;
    float acc = att_init[j];
    #pragma unroll 8
    for (int t = 0; t < TS_; t++) {
        acc += g_kinc[t * 640 + j];
        g_kinc[t * 640 + j] = acc;
        out[OFF_ATTK + t * 640 + j] = acc;
    }
}

// ---------------- K3: phi ----------------
__global__ __launch_bounds__(512) void k_phi() {
    __shared__ float sa[10], sb[10], sk[10];
    int row = blockIdx.x;
    int tid = threadIdx.x;
    if (tid < 10)       sa[tid]      = g_a   [row * 10 + tid];
    else if (tid < 20)  sb[tid - 10] = g_b2  [row * 10 + tid - 10];
    else if (tid < 30)  sk[tid - 20] = g_kinc[row * 10 + tid - 20];
    __syncthreads();
    float s = (float)tid;
    float acc = 0.f;
    #pragma unroll
    for (int k = 0; k < 10; k++) {
        float d = sk[k] - s;
        float e = sb[k] * d * d;
        if (e < 30.f) acc += sa[k] * ex2f(-e);
    }
    g_phi[row * 512 + tid] = acc;
}

// ---------------- GEMM common (R3 proven): 128x128 tile, 8x8/thread, f32x2 ----------------
#define AST 264
#define BST 132

__global__ __launch_bounds__(256, 2) void k_gemm_w(
    const float* __restrict__ c_inp, float* __restrict__ outw)
{
    __shared__ float As2[16 * AST];
    __shared__ float Bs [16 * BST];
    int tid = threadIdx.x;
    int b  = blockIdx.z;
    int m0 = blockIdx.y * 128, n0 = blockIdx.x * 128;

    int lrow = tid >> 2, lq = tid & 3;
    const float* Ap0 = g_phi + b * 512 + (m0 + lrow) * 32768 + lq * 4;
    const float* Ap1 = Ap0 + 64 * 32768;
    int lk = tid >> 5, nq = tid & 31;
    const float* Bp0 = c_inp + b * 512 + lk * 32768 + n0 + nq * 4;
    const float* Bp1 = Bp0 + 8 * 32768;

    float4 aR0 = *(const float4*)(Ap0);
    float4 aR1 = *(const float4*)(Ap1);
    float4 bR0 = *(const float4*)(Bp0);
    float4 bR1 = *(const float4*)(Bp1);

    int tx = tid & 15, ty = tid >> 4;
    u64 acc[8][4];
    #pragma unroll
    for (int i = 0; i < 8; i++)
        #pragma unroll
        for (int j = 0; j < 4; j++) acc[i][j] = 0ull;

    for (int kt = 0; kt < 32; kt++) {
        __syncthreads();
        {
            int m = 2 * lrow;
            *(u64*)&As2[(lq * 4 + 0) * AST + m]       = pack2(aR0.x, aR0.x);
            *(u64*)&As2[(lq * 4 + 1) * AST + m]       = pack2(aR0.y, aR0.y);
            *(u64*)&As2[(lq * 4 + 2) * AST + m]       = pack2(aR0.z, aR0.z);
            *(u64*)&As2[(lq * 4 + 3) * AST + m]       = pack2(aR0.w, aR0.w);
            *(u64*)&As2[(lq * 4 + 0) * AST + m + 128] = pack2(aR1.x, aR1.x);
            *(u64*)&As2[(lq * 4 + 1) * AST + m + 128] = pack2(aR1.y, aR1.y);
            *(u64*)&As2[(lq * 4 + 2) * AST + m + 128] = pack2(aR1.z, aR1.z);
            *(u64*)&As2[(lq * 4 + 3) * AST + m + 128] = pack2(aR1.w, aR1.w);
            *(float4*)&Bs[lk * BST + nq * 4]       = bR0;
            *(float4*)&Bs[(lk + 8) * BST + nq * 4] = bR1;
        }
        __syncthreads();
        if (kt < 31) {
            aR0 = *(const float4*)(Ap0 + (kt + 1) * 16);
            aR1 = *(const float4*)(Ap1 + (kt + 1) * 16);
            bR0 = *(const float4*)(Bp0 + (kt + 1) * 16 * 32768);
            bR1 = *(const float4*)(Bp1 + (kt + 1) * 16 * 32768);
        }
        #pragma unroll
        for (int kk = 0; kk < 16; kk++) {
            ulonglong2 a01 = *(const ulonglong2*)&As2[kk * AST + 8 * ty];
            ulonglong2 a23 = *(const ulonglong2*)&As2[kk * AST + 8 * ty + 4];
            ulonglong2 a45 = *(const ulonglong2*)&As2[kk * AST + 8 * ty + 128];
            ulonglong2 a67 = *(const ulonglong2*)&As2[kk * AST + 8 * ty + 132];
            ulonglong2 b01 = *(const ulonglong2*)&Bs[kk * BST + tx * 4];
            ulonglong2 b23 = *(const ulonglong2*)&Bs[kk * BST + tx * 4 + 64];
            u64 av[8] = {a01.x, a01.y, a23.x, a23.y, a45.x, a45.y, a67.x, a67.y};
            u64 bv[4] = {b01.x, b01.y, b23.x, b23.y};
            #pragma unroll
            for (int i = 0; i < 8; i++)
                #pragma unroll
                for (int j = 0; j < 4; j++)
                    acc[i][j] = ffma2(av[i], bv[j], acc[i][j]);
        }
    }
    float* C = outw + b * 512;
    #pragma unroll
    for (int i = 0; i < 8; i++) {
        int m = m0 + ((i < 4) ? (ty * 4 + i) : (ty * 4 + 64 + i - 4));
        float c0, c1, c2, c3;
        unpack2(acc[i][0], c0, c1); unpack2(acc[i][1], c2, c3);
        *(float4*)&C[(size_t)m * 32768 + n0 + tx * 4] = make_float4(c0, c1, c2, c3);
        unpack2(acc[i][2], c0, c1); unpack2(acc[i][3], c2, c3);
        *(float4*)&C[(size_t)m * 32768 + n0 + tx * 4 + 64] = make_float4(c0, c1, c2, c3);
    }
}

__global__ __launch_bounds__(256, 2) void k_gemm_gi(
    const float* __restrict__ w, const float* __restrict__ W_ih,
    const float* __restrict__ b_ih)
{
    __shared__ float As2[16 * AST];
    __shared__ float Bs [16 * BST];
    int tid = threadIdx.x;
    int m0 = blockIdx.y * 128, n0 = blockIdx.x * 128;

    int lrow = tid >> 2, lq = tid & 3;
    const float* Ap0 = w + (m0 + lrow) * 512 + lq * 4;
    const float* Ap1 = Ap0 + 64 * 512;
    const float* Bp0 = W_ih + (n0 + lrow) * 512 + lq * 4;
    const float* Bp1 = Bp0 + 64 * 512;

    float4 aR0 = *(const float4*)(Ap0);
    float4 aR1 = *(const float4*)(Ap1);
    float4 bR0 = *(const float4*)(Bp0);
    float4 bR1 = *(const float4*)(Bp1);

    int tx = tid & 15, ty = tid >> 4;
    u64 acc[8][4];
    #pragma unroll
    for (int i = 0; i < 8; i++)
        #pragma unroll
        for (int j = 0; j < 4; j++) acc[i][j] = 0ull;

    for (int kt = 0; kt < 32; kt++) {
        __syncthreads();
        {
            int m = 2 * lrow;
            *(u64*)&As2[(lq * 4 + 0) * AST + m]       = pack2(aR0.x, aR0.x);
            *(u64*)&As2[(lq * 4 + 1) * AST + m]       = pack2(aR0.y, aR0.y);
            *(u64*)&As2[(lq * 4 + 2) * AST + m]       = pack2(aR0.z, aR0.z);
            *(u64*)&As2[(lq * 4 + 3) * AST + m]       = pack2(aR0.w, aR0.w);
            *(u64*)&As2[(lq * 4 + 0) * AST + m + 128] = pack2(aR1.x, aR1.x);
            *(u64*)&As2[(lq * 4 + 1) * AST + m + 128] = pack2(aR1.y, aR1.y);
            *(u64*)&As2[(lq * 4 + 2) * AST + m + 128] = pack2(aR1.z, aR1.z);
            *(u64*)&As2[(lq * 4 + 3) * AST + m + 128] = pack2(aR1.w, aR1.w);
            Bs[(lq * 4 + 0) * BST + lrow]       = bR0.x;
            Bs[(lq * 4 + 1) * BST + lrow]       = bR0.y;
            Bs[(lq * 4 + 2) * BST + lrow]       = bR0.z;
            Bs[(lq * 4 + 3) * BST + lrow]       = bR0.w;
            Bs[(lq * 4 + 0) * BST + lrow + 64]  = bR1.x;
            Bs[(lq * 4 + 1) * BST + lrow + 64]  = bR1.y;
            Bs[(lq * 4 + 2) * BST + lrow + 64]  = bR1.z;
            Bs[(lq * 4 + 3) * BST + lrow + 64]  = bR1.w;
        }
        __syncthreads();
        if (kt < 31) {
            aR0 = *(const float4*)(Ap0 + (kt + 1) * 16);
            aR1 = *(const float4*)(Ap1 + (kt + 1) * 16);
            bR0 = *(const float4*)(Bp0 + (kt + 1) * 16);
            bR1 = *(const float4*)(Bp1 + (kt + 1) * 16);
        }
        #pragma unroll
        for (int kk = 0; kk < 16; kk++) {
            ulonglong2 a01 = *(const ulonglong2*)&As2[kk * AST + 8 * ty];
            ulonglong2 a23 = *(const ulonglong2*)&As2[kk * AST + 8 * ty + 4];
            ulonglong2 a45 = *(const ulonglong2*)&As2[kk * AST + 8 * ty + 128];
            ulonglong2 a67 = *(const ulonglong2*)&As2[kk * AST + 8 * ty + 132];
            ulonglong2 b01 = *(const ulonglong2*)&Bs[kk * BST + tx * 4];
            ulonglong2 b23 = *(const ulonglong2*)&Bs[kk * BST + tx * 4 + 64];
            u64 av[8] = {a01.x, a01.y, a23.x, a23.y, a45.x, a45.y, a67.x, a67.y};
            u64 bv[4] = {b01.x, b01.y, b23.x, b23.y};
            #pragma unroll
            for (int i = 0; i < 8; i++)
                #pragma unroll
                for (int j = 0; j < 4; j++)
                    acc[i][j] = ffma2(av[i], bv[j], acc[i][j]);
        }
    }
    float4 bias0 = *(const float4*)&b_ih[n0 + tx * 4];
    float4 bias1 = *(const float4*)&b_ih[n0 + tx * 4 + 64];
    #pragma unroll
    for (int i = 0; i < 8; i++) {
        int m = m0 + ((i < 4) ? (ty * 4 + i) : (ty * 4 + 64 + i - 4));
        float c0, c1, c2, c3;
        unpack2(acc[i][0], c0, c1); unpack2(acc[i][1], c2, c3);
        *(float4*)&g_gi[(size_t)m * 1536 + n0 + tx * 4] =
            make_float4(c0 + bias0.x, c1 + bias0.y, c2 + bias0.z, c3 + bias0.w);
        unpack2(acc[i][2], c0, c1); unpack2(acc[i][3], c2, c3);
        *(float4*)&g_gi[(size_t)m * 1536 + n0 + tx * 4 + 64] =
            make_float4(c0 + bias1.x, c1 + bias1.y, c2 + bias1.z, c3 + bias1.w);
    }
}

// ---------------- K6: persistent GRU, 16-block barrier groups ----------------
// grid (16 ug, 8 bg) x 128 threads; block owns 32 units x 8 batches.
// thread: u = tid>>2 (32 units), bp = tid&3, batches bp and bp+4.
// W slice 96 rows x 516 (198KB) + single h buffer 8 x 516 (16.5KB) = 214.7KB.
#define HS_ST 516
#define SMEM_GRU_BYTES ((96 + 8) * HS_ST * 4)

__global__ __launch_bounds__(128, 1) void k_gru(
    const float* __restrict__ gru_init,
    const float* __restrict__ W_hh, const float* __restrict__ b_hh,
    float* __restrict__ out)
{
    extern __shared__ float smemf[];
    float* hs  = smemf;              // [8][HS_ST]
    float* Wsm = smemf + 8 * HS_ST;  // [96][HS_ST], row = gate*32 + u
    int tid = threadIdx.x;
    int ug = blockIdx.x, bg = blockIdx.y;

    // stage W_hh slice (96 rows x 512)
    for (int f = tid; f < 96 * 128; f += 128) {
        int rr = f >> 7, c = f & 127;
        int gate = rr >> 5, uu = rr & 31;
        float4 v = *(const float4*)&W_hh[((size_t)(gate * 512 + ug * 32 + uu)) * 512 + c * 4];
        *(float4*)&Wsm[rr * HS_ST + c * 4] = v;
    }

    int u  = tid >> 2;          // 0..31, 8 distinct per warp (128B w-LDS)
    int bp = tid & 3;           // 0..3, 4 distinct per warp (64B h-LDS)
    int gu  = ug * 32 + u;
    int gb0 = bg * 8 + bp;
    int gb1 = gb0 + 4;
    float bhr = b_hh[gu], bhz = b_hh[512 + gu], bhn = b_hh[1024 + gu];
    const float* wr = &Wsm[(0  + u) * HS_ST];
    const float* wz = &Wsm[(32 + u) * HS_ST];
    const float* wn = &Wsm[(64 + u) * HS_ST];
    const float* h0 = &hs[bp * HS_ST];
    const float* h1 = &hs[(bp + 4) * HS_ST];
    unsigned bar_target = 0;
    volatile unsigned* bar = &g_bar8[bg * 16];
    __syncthreads();

    for (int t = 0; t < TS_; t++) {
        // gi prefetch (6 scalars)
        const float* gp0 = g_gi + ((size_t)(t * 64 + gb0)) * 1536 + gu;
        const float* gp1 = g_gi + ((size_t)(t * 64 + gb1)) * 1536 + gu;
        float giR0 = __ldcs(gp0), giZ0 = __ldcs(gp0 + 512), giN0 = __ldcs(gp0 + 1024);
        float giR1 = __ldcs(gp1), giZ1 = __ldcs(gp1 + 512), giN1 = __ldcs(gp1 + 1024);

        // stage h_{t-1}: 8 rows x 512 = 1024 float4 / 128 threads
        const float4* src = (t == 0)
            ? (const float4*)(gru_init + bg * 4096)
            : (const float4*)(g_h + (t & 1) * 32768 + bg * 4096);
        #pragma unroll
        for (int c = 0; c < 8; c++) {
            int i = c * 128 + tid;
            float4 v = __ldcg(&src[i]);
            *(float4*)&hs[(i >> 7) * HS_ST + (i & 127) * 4] = v;
        }
        __syncthreads();

        u64 aR0 = 0, aZ0 = 0, aN0 = 0, aR1 = 0, aZ1 = 0, aN1 = 0;
        #pragma unroll 8
        for (int hh = 0; hh < 512; hh += 4) {
            ulonglong2 hv0 = *(const ulonglong2*)&h0[hh];
            ulonglong2 hv1 = *(const ulonglong2*)&h1[hh];
            ulonglong2 r2 = *(const ulonglong2*)&wr[hh];
            ulonglong2 z2 = *(const ulonglong2*)&wz[hh];
            ulonglong2 n2 = *(const ulonglong2*)&wn[hh];
            aR0 = ffma2(hv0.x, r2.x, aR0); aR0 = ffma2(hv0.y, r2.y, aR0);
            aZ0 = ffma2(hv0.x, z2.x, aZ0); aZ0 = ffma2(hv0.y, z2.y, aZ0);
            aN0 = ffma2(hv0.x, n2.x, aN0); aN0 = ffma2(hv0.y, n2.y, aN0);
            aR1 = ffma2(hv1.x, r2.x, aR1); aR1 = ffma2(hv1.y, r2.y, aR1);
            aZ1 = ffma2(hv1.x, z2.x, aZ1); aZ1 = ffma2(hv1.y, z2.y, aZ1);
            aN1 = ffma2(hv1.x, n2.x, aN1); aN1 = ffma2(hv1.y, n2.y, aN1);
        }
        float lo, hi;
        unpack2(aR0, lo, hi); float sR0 = lo + hi;
        unpack2(aZ0, lo, hi); float sZ0 = lo + hi;
        unpack2(aN0, lo, hi); float sN0 = lo + hi;
        unpack2(aR1, lo, hi); float sR1 = lo + hi;
        unpack2(aZ1, lo, hi); float sZ1 = lo + hi;
        unpack2(aN1, lo, hi); float sN1 = lo + hi;

        float hp0 = h0[gu];
        float hp1 = h1[gu];
        float r0 = sigmf(giR0 + sR0 + bhr);
        float z0 = sigmf(giZ0 + sZ0 + bhz);
        float n0v = tanhf(giN0 + r0 * (sN0 + bhn));
        float hn0 = (1.f - z0) * n0v + z0 * hp0;
        float r1 = sigmf(giR1 + sR1 + bhr);
        float z1 = sigmf(giZ1 + sZ1 + bhz);
        float n1v = tanhf(giN1 + r1 * (sN1 + bhn));
        float hn1 = (1.f - z1) * n1v + z1 * hp1;

        if (t < TS_ - 1) {
            g_h[((t + 1) & 1) * 32768 + gb0 * 512 + gu] = hn0;
            g_h[((t + 1) & 1) * 32768 + gb1 * 512 + gu] = hn1;
            __threadfence();                      // drains only the 2 h STGs
            __syncthreads();
            if (tid == 0) {
                bar_target += 16;
                atomicAdd((unsigned*)bar, 1u);
            }
            out[(size_t)t * 32768 + gb0 * 512 + gu] = hn0;
            out[(size_t)t * 32768 + gb1 * 512 + gu] = hn1;
            if (tid == 0) {
                while (*bar < bar_target) { }     // hot spin
            }
            __syncthreads();
        } else {
            out[(size_t)t * 32768 + gb0 * 512 + gu] = hn0;
            out[(size_t)t * 32768 + gb1 * 512 + gu] = hn1;
        }
    }
}

// ---------------- host ----------------
extern "C" void kernel_launch(void* const* d_in, const int* in_sizes, int n_in,
                              void* d_out, int out_size)
{
    const float* c_inp    = (const float*)d_in[0];
    const float* inp      = (const float*)d_in[1];
    const float* gru_init = (const float*)d_in[2];
    const float* att_init = (const float*)d_in[3];
    const float* Wa = (const float*)d_in[4];  const float* ba = (const float*)d_in[5];
    const float* Wb = (const float*)d_in[6];  const float* bb = (const float*)d_in[7];
    const float* Wk = (const float*)d_in[8];  const float* bk = (const float*)d_in[9];
    const float* W_ih = (const float*)d_in[10]; const float* b_ih = (const float*)d_in[11];
    const float* W_hh = (const float*)d_in[12]; const float* b_hh = (const float*)d_in[13];
    float* out = (float*)d_out;

    cudaFuncSetAttribute(k_gru, cudaFuncAttributeMaxDynamicSharedMemorySize, SMEM_GRU_BYTES);

    k_init   <<<1, 128>>>();
    k_abk    <<<2048, 256>>>(inp, Wa, ba, Wb, bb, Wk, bk);
    k_cumsum <<<5, 128>>>(att_init, out);
    k_phi    <<<16384, 512>>>();
    k_gemm_w <<<dim3(4, 2, 64), 256>>>(c_inp, out + OFF_ATTW);
    k_gemm_gi<<<dim3(12, 128), 256>>>(out + OFF_ATTW, W_ih, b_ih);
    k_gru    <<<dim3(16, 8), 128, SMEM_GRU_BYTES>>>(gru_init, W_hh, b_hh, out);
}